// round 2
// baseline (speedup 1.0000x reference)
#include <cuda_runtime.h>
#include <cuda_bf16.h>
#include <math.h>

#define F_N   10000
#define H_N   64
#define G_N   (4 * H_N)      // 256 gates
#define IN_N  (H_N + 1)      // 65
#define W_ELEMS (G_N * IN_N) // 16640 floats per feature
#define W_VEC4  (W_ELEMS / 4) // 4160 float4s
#define OUT_PRED_OFF 0
#define OUT_H_OFF    2
#define OUT_C_OFF    (2 + F_N * H_N)

__device__ float g_sumC[H_N];
__device__ float g_sumH[H_N];

__device__ __forceinline__ float sigmoidf_(float x) {
    return 1.0f / (1.0f + expf(-x));
}

__global__ void zero_kernel() {
    int t = threadIdx.x;
    if (t < H_N) { g_sumC[t] = 0.0f; g_sumH[t] = 0.0f; }
}

__global__ __launch_bounds__(256) void cell_kernel(
    const int*  __restrict__ tim_p,
    const float* __restrict__ X,
    const int*  __restrict__ mask,
    const int*  __restrict__ last_occ,
    const float* __restrict__ Ht,
    const float* __restrict__ c_t,
    const float* __restrict__ W,       // [F, 256, 65]
    const float* __restrict__ Bias,    // [F, 256]
    const float* __restrict__ xTw,     // [F, 64]
    const float* __restrict__ xTb,     // [F, 64]
    const float* __restrict__ delTw,   // [F, 128]
    const float* __restrict__ cinw,    // [F, 64]
    const float* __restrict__ cfw,     // [F, 64]
    const float* __restrict__ coutw,   // [F, 64]
    float* __restrict__ out)           // full output buffer
{
    extern __shared__ float s_w[];     // 16640 floats = 66560 B
    __shared__ float s_in[IN_N];       // [X[f], Ht[f,:]]
    __shared__ float s_gates[G_N];
    __shared__ float s_ct[H_N];

    const int f   = blockIdx.x;
    const int tid = threadIdx.x;

    // ---- stage inputs ----
    if (tid == 0) s_in[0] = X[f];
    if (tid < H_N) {
        s_in[1 + tid] = Ht[(size_t)f * H_N + tid];
        s_ct[tid]     = c_t[tid];
    }

    // ---- stage weight tile: fully coalesced float4 stream ----
    {
        const float4* src = (const float4*)(W + (size_t)f * W_ELEMS);
        float4* dst = (float4*)s_w;
        #pragma unroll
        for (int i = 0; i < W_VEC4 / 256; i++)          // 16 full rounds
            dst[i * 256 + tid] = src[i * 256 + tid];
        {   // tail: 4160 - 16*256 = 64
            int i = (W_VEC4 / 256) * 256 + tid;
            if (tid < (W_VEC4 & 255)) dst[i] = src[i];
        }
    }
    __syncthreads();

    // ---- mat-vec from smem: one gate row per thread ----
    // row stride 65 floats; 65 mod 32 == 1 -> bank-conflict-free across lanes.
    {
        const float* row = s_w + tid * IN_N;
        float acc = 0.0f;
        #pragma unroll
        for (int k = 0; k < IN_N; k++)
            acc += row[k] * s_in[k];
        s_gates[tid] = acc + Bias[(size_t)f * G_N + tid];
    }
    __syncthreads();

    // ---- cell elementwise, 64 threads ----
    if (tid < H_N) {
        const int h = tid;
        const size_t fh = (size_t)f * H_N + h;
        const float ct    = s_ct[h];
        const float delta = (float)(*tim_p) - (float)last_occ[f];

        const float gi     = sigmoidf_(s_gates[h]         + cinw[fh] * ct);
        const float gf     = sigmoidf_(s_gates[H_N + h]   + cfw[fh]  * ct);
        const float go_pre = s_gates[2 * H_N + h];
        const float pre_c  = tanhf(s_gates[3 * H_N + h]);

        const float xmT = xTw[fh] * s_in[0] + xTb[fh];
        const float dTt = delTw[(size_t)f * 2 * H_N + h]       * delta;
        const float dTo = delTw[(size_t)f * 2 * H_N + H_N + h] * delta;
        const float Tt  = sigmoidf_(xmT + dTt);

        const float aggc = gf * ct + gi * Tt * pre_c;
        const float go   = sigmoidf_(go_pre + coutw[fh] * aggc + dTo);
        const float hn   = go * tanhf(aggc);

        const float mf = (mask[f] == 1) ? 1.0f : 0.0f;
        out[OUT_H_OFF + fh] = mf * hn;
        if (mf != 0.0f) {
            atomicAdd(&g_sumC[h], aggc);
            atomicAdd(&g_sumH[h], hn);
        }
    }
}

__global__ __launch_bounds__(128) void head_kernel(
    const int*  __restrict__ mask,
    const float* __restrict__ w1,   // [128,128]
    const float* __restrict__ b1,   // [128]
    const float* __restrict__ w2,   // [2,128]
    const float* __restrict__ b2,   // [2]
    float* __restrict__ out)
{
    const int tid = threadIdx.x;
    __shared__ float s_inp[2 * H_N];
    __shared__ float s_hid[2 * H_N];
    __shared__ int   s_red[128];
    __shared__ float s_log[2];

    // count observed features
    int c = 0;
    for (int i = tid; i < F_N; i += 128) c += (mask[i] == 1);
    s_red[tid] = c;
    __syncthreads();
    #pragma unroll
    for (int o = 64; o > 0; o >>= 1) {
        if (tid < o) s_red[tid] += s_red[tid + o];
        __syncthreads();
    }
    const float cnt = fmaxf((float)s_red[0], 1.0f);

    if (tid < H_N) {
        const float Cc = g_sumC[tid] / cnt;
        const float Hm = g_sumH[tid] / cnt;
        s_inp[tid]       = Cc;
        s_inp[H_N + tid] = Hm;
        out[OUT_C_OFF + tid] = Cc;
    }
    __syncthreads();

    // hidden = relu(w1 @ inp + b1)
    {
        float acc = b1[tid];
        #pragma unroll 8
        for (int k = 0; k < 2 * H_N; k++)
            acc += w1[tid * (2 * H_N) + k] * s_inp[k];
        s_hid[tid] = fmaxf(acc, 0.0f);
    }
    __syncthreads();

    if (tid < 2) {
        float l = b2[tid];
        for (int k = 0; k < 2 * H_N; k++)
            l += w2[tid * (2 * H_N) + k] * s_hid[k];
        s_log[tid] = l;
    }
    __syncthreads();

    if (tid == 0) {
        const float m  = fmaxf(s_log[0], s_log[1]);
        const float e0 = expf(s_log[0] - m);
        const float e1 = expf(s_log[1] - m);
        const float inv = 1.0f / (e0 + e1);
        out[OUT_PRED_OFF + 0] = e0 * inv;
        out[OUT_PRED_OFF + 1] = e1 * inv;
    }
}

extern "C" void kernel_launch(void* const* d_in, const int* in_sizes, int n_in,
                              void* d_out, int out_size) {
    const int*   tim       = (const int*)  d_in[0];
    const float* X         = (const float*)d_in[1];
    // d_in[2] = X_hap (unused by reference)
    const int*   mask      = (const int*)  d_in[3];
    const int*   last_occ  = (const int*)  d_in[4];
    const float* Ht        = (const float*)d_in[5];
    // d_in[6] = Ct (unused by reference)
    const float* c_t       = (const float*)d_in[7];
    const float* W         = (const float*)d_in[8];
    const float* Bias      = (const float*)d_in[9];
    const float* xTw       = (const float*)d_in[10];
    const float* xTb       = (const float*)d_in[11];
    const float* delTw     = (const float*)d_in[12];
    const float* cinw      = (const float*)d_in[13];
    const float* cfw       = (const float*)d_in[14];
    const float* coutw     = (const float*)d_in[15];
    const float* w1        = (const float*)d_in[16];
    const float* b1        = (const float*)d_in[17];
    const float* w2        = (const float*)d_in[18];
    const float* b2        = (const float*)d_in[19];
    float* out = (float*)d_out;

    const int smem_bytes = W_ELEMS * sizeof(float);   // 66560
    cudaFuncSetAttribute(cell_kernel,
                         cudaFuncAttributeMaxDynamicSharedMemorySize, smem_bytes);

    zero_kernel<<<1, 128>>>();
    cell_kernel<<<F_N, 256, smem_bytes>>>(tim, X, mask, last_occ, Ht, c_t,
                                          W, Bias, xTw, xTb, delTw, cinw, cfw, coutw, out);
    head_kernel<<<1, 128>>>(mask, w1, b1, w2, b2, out);
}

// round 3
// speedup vs baseline: 1.5077x; 1.5077x over previous
#include <cuda_runtime.h>
#include <cuda_bf16.h>
#include <math.h>
#include <stdint.h>

#define F_N   10000
#define H_N   64
#define G_N   (4 * H_N)          // 256 gate rows
#define IN_N  (H_N + 1)          // 65
#define W_ELEMS (G_N * IN_N)     // 16640 floats
#define OUT_PRED_OFF 0
#define OUT_H_OFF    2
#define OUT_C_OFF    (2 + F_N * H_N)

#define GRID_C 148
#define NSTAGE 3
#define MAXNF  68                // max features per CTA

// per-stage float offsets inside a stage buffer
#define W_OFF     0
#define BIAS_OFF  (W_ELEMS)                  // 16640  (256 floats)
#define HT_OFF    (BIAS_OFF + G_N)           // 16896  (64)
#define XTW_OFF   (HT_OFF + H_N)             // 16960  (64)
#define XTB_OFF   (XTW_OFF + H_N)            // 17024  (64)
#define DELT_OFF  (XTB_OFF + H_N)            // 17088  (128)
#define CIN_OFF   (DELT_OFF + 2 * H_N)       // 17216  (64)
#define CF_OFF    (CIN_OFF + H_N)            // 17280  (64)
#define COUT_OFF  (CF_OFF + H_N)             // 17344  (64)
#define STAGE_F   (COUT_OFF + H_N)           // 17408 floats = 69632 B
#define STAGE_B   (STAGE_F * 4)

__device__ float g_sumC[H_N];
__device__ float g_sumH[H_N];

__device__ __forceinline__ float sigmoidf_(float x) {
    return 1.0f / (1.0f + expf(-x));
}

__device__ __forceinline__ uint32_t smem_u32(const void* p) {
    uint32_t a;
    asm("{ .reg .u64 t; cvta.to.shared.u64 t, %1; cvt.u32.u64 %0, t; }"
        : "=r"(a) : "l"(p));
    return a;
}

__device__ __forceinline__ void mbar_init(uint32_t mbar, uint32_t cnt) {
    asm volatile("mbarrier.init.shared.b64 [%0], %1;" :: "r"(mbar), "r"(cnt) : "memory");
}
__device__ __forceinline__ void mbar_expect_tx(uint32_t mbar, uint32_t bytes) {
    asm volatile("mbarrier.arrive.expect_tx.shared.b64 _, [%0], %1;"
                 :: "r"(mbar), "r"(bytes) : "memory");
}
__device__ __forceinline__ void mbar_wait(uint32_t mbar, uint32_t parity) {
    uint32_t done;
    asm volatile(
        "{\n\t.reg .pred p;\n\t"
        "mbarrier.try_wait.parity.acquire.cta.shared::cta.b64 p, [%1], %2;\n\t"
        "selp.b32 %0, 1, 0, p;\n\t}"
        : "=r"(done) : "r"(mbar), "r"(parity) : "memory");
    if (!done) {
        asm volatile(
            "{\n\t.reg .pred P1;\n\t"
            "W_%=:\n\t"
            "mbarrier.try_wait.parity.acquire.cta.shared::cta.b64 P1, [%0], %1, 0x989680;\n\t"
            "@P1 bra.uni D_%=;\n\t"
            "bra.uni W_%=;\n\t"
            "D_%=:\n\t}"
            :: "r"(mbar), "r"(parity) : "memory");
    }
}
__device__ __forceinline__ void bulk_cp(uint32_t dst, const void* src,
                                        uint32_t bytes, uint32_t mbar) {
    asm volatile(
        "cp.async.bulk.shared::cta.global.mbarrier::complete_tx::bytes [%0], [%1], %2, [%3];"
        :: "r"(dst), "l"(src), "r"(bytes), "r"(mbar) : "memory");
}

__global__ void zero_kernel() {
    int t = threadIdx.x;
    if (t < H_N) { g_sumC[t] = 0.0f; g_sumH[t] = 0.0f; }
}

__global__ __launch_bounds__(256, 1) void cell_kernel(
    const int*  __restrict__ tim_p,
    const float* __restrict__ X,
    const int*  __restrict__ mask,
    const int*  __restrict__ last_occ,
    const float* __restrict__ Ht,
    const float* __restrict__ c_t,
    const float* __restrict__ W,       // [F, 256, 65]
    const float* __restrict__ Bias,    // [F, 256]
    const float* __restrict__ xTw,     // [F, 64]
    const float* __restrict__ xTb,     // [F, 64]
    const float* __restrict__ delTw,   // [F, 128]
    const float* __restrict__ cinw,    // [F, 64]
    const float* __restrict__ cfw,     // [F, 64]
    const float* __restrict__ coutw,   // [F, 64]
    float* __restrict__ out)
{
    extern __shared__ float s_buf[];           // NSTAGE * STAGE_F floats
    __shared__ float s_gates[G_N];
    __shared__ float s_ct[H_N];
    __shared__ float s_X[MAXNF];
    __shared__ float s_delta[MAXNF];
    __shared__ float s_mf[MAXNF];
    __shared__ __align__(8) uint64_t s_mbar[NSTAGE];

    const int bid = blockIdx.x;
    const int tid = threadIdx.x;
    const int nf  = (F_N - bid + GRID_C - 1) / GRID_C;

    // ---- prologue: gather per-feature scalars, c_t, init barriers ----
    {
        const int tim = *tim_p;
        for (int j = tid; j < nf; j += 256) {
            const int f = bid + j * GRID_C;
            s_X[j]     = X[f];
            s_delta[j] = (float)tim - (float)last_occ[f];
            s_mf[j]    = (mask[f] == 1) ? 1.0f : 0.0f;
        }
    }
    if (tid < H_N) s_ct[tid] = c_t[tid];
    if (tid == 0) {
        for (int s = 0; s < NSTAGE; s++) mbar_init(smem_u32(&s_mbar[s]), 1);
    }
    __syncthreads();
    if (tid == 0) {
        asm volatile("fence.proxy.async.shared::cta;" ::: "memory");
    }

    const uint32_t sbase = smem_u32(s_buf);

    // issue prefetch for feature index j into stage j%NSTAGE
    auto issue = [&](int j) {
        const int s = j % NSTAGE;
        const size_t f = (size_t)(bid + j * GRID_C);
        const uint32_t d = sbase + (uint32_t)s * STAGE_B;
        const uint32_t mb = smem_u32(&s_mbar[s]);
        mbar_expect_tx(mb, STAGE_B);
        bulk_cp(d + W_OFF * 4,    W     + f * W_ELEMS,   W_ELEMS * 4, mb);
        bulk_cp(d + BIAS_OFF * 4, Bias  + f * G_N,       G_N * 4,     mb);
        bulk_cp(d + HT_OFF * 4,   Ht    + f * H_N,       H_N * 4,     mb);
        bulk_cp(d + XTW_OFF * 4,  xTw   + f * H_N,       H_N * 4,     mb);
        bulk_cp(d + XTB_OFF * 4,  xTb   + f * H_N,       H_N * 4,     mb);
        bulk_cp(d + DELT_OFF * 4, delTw + f * 2 * H_N,   2 * H_N * 4, mb);
        bulk_cp(d + CIN_OFF * 4,  cinw  + f * H_N,       H_N * 4,     mb);
        bulk_cp(d + CF_OFF * 4,   cfw   + f * H_N,       H_N * 4,     mb);
        bulk_cp(d + COUT_OFF * 4, coutw + f * H_N,       H_N * 4,     mb);
    };

    if (tid == 0) {
        const int pre = (nf < NSTAGE) ? nf : NSTAGE;
        for (int j = 0; j < pre; j++) issue(j);
    }

    // ---- main loop ----
    for (int j = 0; j < nf; j++) {
        const int s  = j % NSTAGE;
        const int ph = (j / NSTAGE) & 1;
        mbar_wait(smem_u32(&s_mbar[s]), ph);

        const float* buf = s_buf + (size_t)s * STAGE_F;

        // gates: one row per thread; stride 65 -> bank-conflict-free
        {
            const float  xv  = s_X[j];
            const float* row = buf + tid * IN_N;
            const float* ht  = buf + HT_OFF;
            float acc = row[0] * xv;
            #pragma unroll
            for (int k = 1; k < IN_N; k++)
                acc += row[k] * ht[k - 1];
            s_gates[tid] = acc + buf[BIAS_OFF + tid];
        }
        __syncthreads();

        if (tid < H_N) {
            const int h = tid;
            const int f = bid + j * GRID_C;
            const float ct    = s_ct[h];
            const float delta = s_delta[j];

            const float gi     = sigmoidf_(s_gates[h]           + buf[CIN_OFF + h] * ct);
            const float gf     = sigmoidf_(s_gates[H_N + h]     + buf[CF_OFF + h]  * ct);
            const float go_pre = s_gates[2 * H_N + h];
            const float pre_c  = tanhf(s_gates[3 * H_N + h]);

            const float xmT = buf[XTW_OFF + h] * s_X[j] + buf[XTB_OFF + h];
            const float dTt = buf[DELT_OFF + h]        * delta;
            const float dTo = buf[DELT_OFF + H_N + h]  * delta;
            const float Tt  = sigmoidf_(xmT + dTt);

            const float aggc = gf * ct + gi * Tt * pre_c;
            const float go   = sigmoidf_(go_pre + buf[COUT_OFF + h] * aggc + dTo);
            const float hn   = go * tanhf(aggc);

            const float mf = s_mf[j];
            out[OUT_H_OFF + (size_t)f * H_N + h] = mf * hn;
            if (mf != 0.0f) {
                atomicAdd(&g_sumC[h], aggc);
                atomicAdd(&g_sumH[h], hn);
            }
        }
        __syncthreads();   // all reads of stage s complete

        if (tid == 0 && j + NSTAGE < nf) issue(j + NSTAGE);
    }
}

__global__ __launch_bounds__(128) void head_kernel(
    const int*  __restrict__ mask,
    const float* __restrict__ w1,   // [128,128]
    const float* __restrict__ b1,   // [128]
    const float* __restrict__ w2,   // [2,128]
    const float* __restrict__ b2,   // [2]
    float* __restrict__ out)
{
    const int tid = threadIdx.x;
    __shared__ float s_inp[2 * H_N];
    __shared__ float s_hid[2 * H_N];
    __shared__ int   s_red[128];
    __shared__ float s_log[2];

    int c = 0;
    for (int i = tid; i < F_N; i += 128) c += (mask[i] == 1);
    s_red[tid] = c;
    __syncthreads();
    #pragma unroll
    for (int o = 64; o > 0; o >>= 1) {
        if (tid < o) s_red[tid] += s_red[tid + o];
        __syncthreads();
    }
    const float cnt = fmaxf((float)s_red[0], 1.0f);

    if (tid < H_N) {
        const float Cc = g_sumC[tid] / cnt;
        const float Hm = g_sumH[tid] / cnt;
        s_inp[tid]       = Cc;
        s_inp[H_N + tid] = Hm;
        out[OUT_C_OFF + tid] = Cc;
    }
    __syncthreads();

    {
        float acc = b1[tid];
        #pragma unroll 8
        for (int k = 0; k < 2 * H_N; k++)
            acc += w1[tid * (2 * H_N) + k] * s_inp[k];
        s_hid[tid] = fmaxf(acc, 0.0f);
    }
    __syncthreads();

    if (tid < 2) {
        float l = b2[tid];
        for (int k = 0; k < 2 * H_N; k++)
            l += w2[tid * (2 * H_N) + k] * s_hid[k];
        s_log[tid] = l;
    }
    __syncthreads();

    if (tid == 0) {
        const float m  = fmaxf(s_log[0], s_log[1]);
        const float e0 = expf(s_log[0] - m);
        const float e1 = expf(s_log[1] - m);
        const float inv = 1.0f / (e0 + e1);
        out[OUT_PRED_OFF + 0] = e0 * inv;
        out[OUT_PRED_OFF + 1] = e1 * inv;
    }
}

extern "C" void kernel_launch(void* const* d_in, const int* in_sizes, int n_in,
                              void* d_out, int out_size) {
    const int*   tim       = (const int*)  d_in[0];
    const float* X         = (const float*)d_in[1];
    // d_in[2] = X_hap (unused)
    const int*   mask      = (const int*)  d_in[3];
    const int*   last_occ  = (const int*)  d_in[4];
    const float* Ht        = (const float*)d_in[5];
    // d_in[6] = Ct (unused)
    const float* c_t       = (const float*)d_in[7];
    const float* W         = (const float*)d_in[8];
    const float* Bias      = (const float*)d_in[9];
    const float* xTw       = (const float*)d_in[10];
    const float* xTb       = (const float*)d_in[11];
    const float* delTw     = (const float*)d_in[12];
    const float* cinw      = (const float*)d_in[13];
    const float* cfw       = (const float*)d_in[14];
    const float* coutw     = (const float*)d_in[15];
    const float* w1        = (const float*)d_in[16];
    const float* b1        = (const float*)d_in[17];
    const float* w2        = (const float*)d_in[18];
    const float* b2        = (const float*)d_in[19];
    float* out = (float*)d_out;

    const int smem_bytes = NSTAGE * STAGE_B;   // 208896
    static int configured = 0;
    if (!configured) {
        cudaFuncSetAttribute(cell_kernel,
                             cudaFuncAttributeMaxDynamicSharedMemorySize, smem_bytes);
        configured = 1;
    }

    zero_kernel<<<1, 128>>>();
    cell_kernel<<<GRID_C, 256, smem_bytes>>>(tim, X, mask, last_occ, Ht, c_t,
                                             W, Bias, xTw, xTb, delTw,
                                             cinw, cfw, coutw, out);
    head_kernel<<<1, 128>>>(mask, w1, b1, w2, b2, out);
}

// round 4
// speedup vs baseline: 1.5701x; 1.0414x over previous
#include <cuda_runtime.h>
#include <cuda_bf16.h>
#include <math.h>
#include <stdint.h>

#define F_N   10000
#define H_N   64
#define G_N   (4 * H_N)          // 256 gate rows
#define IN_N  (H_N + 1)          // 65
#define W_ELEMS (G_N * IN_N)     // 16640 floats
#define OUT_PRED_OFF 0
#define OUT_H_OFF    2
#define OUT_C_OFF    (2 + F_N * H_N)

#define GRID_C 148
#define NSTAGE 3
#define MAXNF  68                // max features per CTA (ceil(10000/148))

// per-stage float offsets inside a stage buffer
#define W_OFF     0
#define BIAS_OFF  (W_ELEMS)                  // 16640  (256 floats)
#define HT_OFF    (BIAS_OFF + G_N)           // 16896  (64)  -> byte 67584, 16B aligned
#define XTW_OFF   (HT_OFF + H_N)             // 16960  (64)
#define XTB_OFF   (XTW_OFF + H_N)            // 17024  (64)
#define DELT_OFF  (XTB_OFF + H_N)            // 17088  (128)
#define CIN_OFF   (DELT_OFF + 2 * H_N)       // 17216  (64)
#define CF_OFF    (CIN_OFF + H_N)            // 17280  (64)
#define COUT_OFF  (CF_OFF + H_N)             // 17344  (64)
#define STAGE_F   (COUT_OFF + H_N)           // 17408 floats = 69632 B
#define STAGE_B   (STAGE_F * 4)

__device__ float g_sumC[H_N];    // zero-initialized at module load; head re-zeros
__device__ float g_sumH[H_N];
__device__ int   g_cnt;

__device__ __forceinline__ float sigmoidf_(float x) {
    return 1.0f / (1.0f + expf(-x));
}

__device__ __forceinline__ uint32_t smem_u32(const void* p) {
    uint32_t a;
    asm("{ .reg .u64 t; cvta.to.shared.u64 t, %1; cvt.u32.u64 %0, t; }"
        : "=r"(a) : "l"(p));
    return a;
}

__device__ __forceinline__ void mbar_init(uint32_t mbar, uint32_t cnt) {
    asm volatile("mbarrier.init.shared.b64 [%0], %1;" :: "r"(mbar), "r"(cnt) : "memory");
}
__device__ __forceinline__ void mbar_expect_tx(uint32_t mbar, uint32_t bytes) {
    asm volatile("mbarrier.arrive.expect_tx.shared.b64 _, [%0], %1;"
                 :: "r"(mbar), "r"(bytes) : "memory");
}
__device__ __forceinline__ void mbar_wait(uint32_t mbar, uint32_t parity) {
    uint32_t done;
    asm volatile(
        "{\n\t.reg .pred p;\n\t"
        "mbarrier.try_wait.parity.acquire.cta.shared::cta.b64 p, [%1], %2;\n\t"
        "selp.b32 %0, 1, 0, p;\n\t}"
        : "=r"(done) : "r"(mbar), "r"(parity) : "memory");
    if (!done) {
        asm volatile(
            "{\n\t.reg .pred P1;\n\t"
            "W_%=:\n\t"
            "mbarrier.try_wait.parity.acquire.cta.shared::cta.b64 P1, [%0], %1, 0x989680;\n\t"
            "@P1 bra.uni D_%=;\n\t"
            "bra.uni W_%=;\n\t"
            "D_%=:\n\t}"
            :: "r"(mbar), "r"(parity) : "memory");
    }
}
__device__ __forceinline__ void bulk_cp(uint32_t dst, const void* src,
                                        uint32_t bytes, uint32_t mbar) {
    asm volatile(
        "cp.async.bulk.shared::cta.global.mbarrier::complete_tx::bytes [%0], [%1], %2, [%3];"
        :: "r"(dst), "l"(src), "r"(bytes), "r"(mbar) : "memory");
}

__global__ __launch_bounds__(256, 1) void cell_kernel(
    const int*  __restrict__ tim_p,
    const float* __restrict__ X,
    const int*  __restrict__ mask,
    const int*  __restrict__ last_occ,
    const float* __restrict__ Ht,
    const float* __restrict__ c_t,
    const float* __restrict__ W,       // [F, 256, 65]
    const float* __restrict__ Bias,    // [F, 256]
    const float* __restrict__ xTw,     // [F, 64]
    const float* __restrict__ xTb,     // [F, 64]
    const float* __restrict__ delTw,   // [F, 128]
    const float* __restrict__ cinw,    // [F, 64]
    const float* __restrict__ cfw,     // [F, 64]
    const float* __restrict__ coutw,   // [F, 64]
    float* __restrict__ out)
{
    extern __shared__ float s_buf[];           // NSTAGE * STAGE_F floats
    __shared__ float s_gates[G_N];
    __shared__ float s_ct[H_N];
    __shared__ float s_X[MAXNF];
    __shared__ float s_delta[MAXNF];
    __shared__ float s_mf[MAXNF];
    __shared__ __align__(8) uint64_t s_mbar[NSTAGE];

    const int bid = blockIdx.x;
    const int tid = threadIdx.x;
    const int nf  = (F_N - bid + GRID_C - 1) / GRID_C;

    // ---- prologue: per-feature scalars, mask count, c_t, barriers ----
    {
        const int tim = *tim_p;
        const int j = tid;                     // nf <= 68 < 256: single pass
        int mbit = 0;
        if (j < nf) {
            const int f = bid + j * GRID_C;
            s_X[j]     = X[f];
            s_delta[j] = (float)tim - (float)last_occ[f];
            mbit       = (mask[f] == 1);
            s_mf[j]    = mbit ? 1.0f : 0.0f;
        }
        const unsigned b = __ballot_sync(0xFFFFFFFFu, mbit != 0);
        if ((tid & 31) == 0 && b) atomicAdd(&g_cnt, __popc(b));
    }
    if (tid < H_N) s_ct[tid] = c_t[tid];
    if (tid == 0) {
        for (int s = 0; s < NSTAGE; s++) mbar_init(smem_u32(&s_mbar[s]), 1);
    }
    __syncthreads();
    if (tid == 0) {
        asm volatile("fence.proxy.async.shared::cta;" ::: "memory");
    }

    const uint32_t sbase = smem_u32(s_buf);

    auto issue = [&](int j) {
        const int s = j % NSTAGE;
        const size_t f = (size_t)(bid + j * GRID_C);
        const uint32_t d = sbase + (uint32_t)s * STAGE_B;
        const uint32_t mb = smem_u32(&s_mbar[s]);
        mbar_expect_tx(mb, STAGE_B);
        bulk_cp(d + W_OFF * 4,    W     + f * W_ELEMS,   W_ELEMS * 4, mb);
        bulk_cp(d + BIAS_OFF * 4, Bias  + f * G_N,       G_N * 4,     mb);
        bulk_cp(d + HT_OFF * 4,   Ht    + f * H_N,       H_N * 4,     mb);
        bulk_cp(d + XTW_OFF * 4,  xTw   + f * H_N,       H_N * 4,     mb);
        bulk_cp(d + XTB_OFF * 4,  xTb   + f * H_N,       H_N * 4,     mb);
        bulk_cp(d + DELT_OFF * 4, delTw + f * 2 * H_N,   2 * H_N * 4, mb);
        bulk_cp(d + CIN_OFF * 4,  cinw  + f * H_N,       H_N * 4,     mb);
        bulk_cp(d + CF_OFF * 4,   cfw   + f * H_N,       H_N * 4,     mb);
        bulk_cp(d + COUT_OFF * 4, coutw + f * H_N,       H_N * 4,     mb);
    };

    if (tid == 0) {
        const int pre = (nf < NSTAGE) ? nf : NSTAGE;
        for (int j = 0; j < pre; j++) issue(j);
    }

    // ---- main loop ----
    for (int j = 0; j < nf; j++) {
        const int s  = j % NSTAGE;
        const int ph = (j / NSTAGE) & 1;
        mbar_wait(smem_u32(&s_mbar[s]), ph);

        const float* buf = s_buf + (size_t)s * STAGE_F;

        // gates: one row/thread. Row loads: stride-65 -> conflict-free.
        // ht operand: contiguous float4 broadcasts (16B-aligned).
        {
            const float  xv  = s_X[j];
            const float* row = buf + tid * IN_N;
            const float4* ht4 = (const float4*)(buf + HT_OFF);
            float acc = row[0] * xv;
            #pragma unroll
            for (int c = 0; c < 16; c++) {
                const float4 h4 = ht4[c];
                acc += row[1 + 4 * c] * h4.x;
                acc += row[2 + 4 * c] * h4.y;
                acc += row[3 + 4 * c] * h4.z;
                acc += row[4 + 4 * c] * h4.w;
            }
            s_gates[tid] = acc + buf[BIAS_OFF + tid];
        }
        __syncthreads();

        if (tid < H_N) {
            const int h = tid;
            const int f = bid + j * GRID_C;
            const float ct    = s_ct[h];
            const float delta = s_delta[j];

            const float gi     = sigmoidf_(s_gates[h]           + buf[CIN_OFF + h] * ct);
            const float gf     = sigmoidf_(s_gates[H_N + h]     + buf[CF_OFF + h]  * ct);
            const float go_pre = s_gates[2 * H_N + h];
            const float pre_c  = tanhf(s_gates[3 * H_N + h]);

            const float xmT = buf[XTW_OFF + h] * s_X[j] + buf[XTB_OFF + h];
            const float dTt = buf[DELT_OFF + h]        * delta;
            const float dTo = buf[DELT_OFF + H_N + h]  * delta;
            const float Tt  = sigmoidf_(xmT + dTt);

            const float aggc = gf * ct + gi * Tt * pre_c;
            const float go   = sigmoidf_(go_pre + buf[COUT_OFF + h] * aggc + dTo);
            const float hn   = go * tanhf(aggc);

            const float mf = s_mf[j];
            out[OUT_H_OFF + (size_t)f * H_N + h] = mf * hn;
            if (mf != 0.0f) {
                atomicAdd(&g_sumC[h], aggc);
                atomicAdd(&g_sumH[h], hn);
            }
        }
        __syncthreads();   // all reads of stage s complete

        if (tid == 0 && j + NSTAGE < nf) issue(j + NSTAGE);
    }
}

__global__ __launch_bounds__(128) void head_kernel(
    const float* __restrict__ w1,   // [128,128]
    const float* __restrict__ b1,   // [128]
    const float* __restrict__ w2,   // [2,128]
    const float* __restrict__ b2,   // [2]
    float* __restrict__ out)
{
    const int tid = threadIdx.x;
    __shared__ float s_inp[2 * H_N];
    __shared__ float s_hid[2 * H_N];
    __shared__ float s_log[2];

    const float cnt = fmaxf((float)g_cnt, 1.0f);

    if (tid < H_N) {
        const float Cc = g_sumC[tid] / cnt;
        const float Hm = g_sumH[tid] / cnt;
        s_inp[tid]       = Cc;
        s_inp[H_N + tid] = Hm;
        out[OUT_C_OFF + tid] = Cc;
    }
    __syncthreads();

    // re-zero accumulators for the next (graph-replayed) launch
    if (tid < H_N) { g_sumC[tid] = 0.0f; g_sumH[tid] = 0.0f; }
    if (tid == H_N) g_cnt = 0;

    // hidden = relu(w1 @ inp + b1)
    {
        float acc = b1[tid];
        #pragma unroll 8
        for (int k = 0; k < 2 * H_N; k++)
            acc += w1[tid * (2 * H_N) + k] * s_inp[k];
        s_hid[tid] = fmaxf(acc, 0.0f);
    }
    __syncthreads();

    if (tid < 2) {
        float l = b2[tid];
        for (int k = 0; k < 2 * H_N; k++)
            l += w2[tid * (2 * H_N) + k] * s_hid[k];
        s_log[tid] = l;
    }
    __syncthreads();

    if (tid == 0) {
        const float m  = fmaxf(s_log[0], s_log[1]);
        const float e0 = expf(s_log[0] - m);
        const float e1 = expf(s_log[1] - m);
        const float inv = 1.0f / (e0 + e1);
        out[OUT_PRED_OFF + 0] = e0 * inv;
        out[OUT_PRED_OFF + 1] = e1 * inv;
    }
}

extern "C" void kernel_launch(void* const* d_in, const int* in_sizes, int n_in,
                              void* d_out, int out_size) {
    const int*   tim       = (const int*)  d_in[0];
    const float* X         = (const float*)d_in[1];
    // d_in[2] = X_hap (unused)
    const int*   mask      = (const int*)  d_in[3];
    const int*   last_occ  = (const int*)  d_in[4];
    const float* Ht        = (const float*)d_in[5];
    // d_in[6] = Ct (unused)
    const float* c_t       = (const float*)d_in[7];
    const float* W         = (const float*)d_in[8];
    const float* Bias      = (const float*)d_in[9];
    const float* xTw       = (const float*)d_in[10];
    const float* xTb       = (const float*)d_in[11];
    const float* delTw     = (const float*)d_in[12];
    const float* cinw      = (const float*)d_in[13];
    const float* cfw       = (const float*)d_in[14];
    const float* coutw     = (const float*)d_in[15];
    const float* w1        = (const float*)d_in[16];
    const float* b1        = (const float*)d_in[17];
    const float* w2        = (const float*)d_in[18];
    const float* b2        = (const float*)d_in[19];
    float* out = (float*)d_out;

    const int smem_bytes = NSTAGE * STAGE_B;   // 208896
    cudaFuncSetAttribute(cell_kernel,
                         cudaFuncAttributeMaxDynamicSharedMemorySize, smem_bytes);

    cell_kernel<<<GRID_C, 256, smem_bytes>>>(tim, X, mask, last_occ, Ht, c_t,
                                             W, Bias, xTw, xTb, delTw,
                                             cinw, cfw, coutw, out);
    head_kernel<<<1, 128>>>(w1, b1, w2, b2, out);
}

// round 5
// speedup vs baseline: 1.6661x; 1.0612x over previous
#include <cuda_runtime.h>
#include <cuda_bf16.h>
#include <math.h>
#include <stdint.h>

#define F_N   10000
#define H_N   64
#define G_N   (4 * H_N)          // 256 gate rows
#define IN_N  (H_N + 1)          // 65
#define W_ELEMS (G_N * IN_N)     // 16640 floats
#define OUT_PRED_OFF 0
#define OUT_H_OFF    2
#define OUT_C_OFF    (2 + F_N * H_N)

#define GRID_C 148
#define NSTAGE 3
#define MAXNF  68                // max features per CTA (ceil(10000/148))

// per-stage float offsets inside a stage buffer
#define W_OFF     0
#define BIAS_OFF  (W_ELEMS)                  // 16640  (256 floats)
#define HT_OFF    (BIAS_OFF + G_N)           // 16896  (64)  -> 16B aligned
#define XTW_OFF   (HT_OFF + H_N)             // 16960
#define XTB_OFF   (XTW_OFF + H_N)            // 17024
#define DELT_OFF  (XTB_OFF + H_N)            // 17088  (128)
#define CIN_OFF   (DELT_OFF + 2 * H_N)       // 17216
#define CF_OFF    (CIN_OFF + H_N)            // 17280
#define COUT_OFF  (CF_OFF + H_N)             // 17344
#define STAGE_F   (COUT_OFF + H_N)           // 17408 floats = 69632 B
#define STAGE_B   (STAGE_F * 4)

__device__ float g_sumC[H_N];    // zero at module load; head re-zeros each run
__device__ float g_sumH[H_N];
__device__ int   g_cnt;

__device__ __forceinline__ float sigmoidf_(float x) {
    return 1.0f / (1.0f + expf(-x));
}

__device__ __forceinline__ uint32_t smem_u32(const void* p) {
    uint32_t a;
    asm("{ .reg .u64 t; cvta.to.shared.u64 t, %1; cvt.u32.u64 %0, t; }"
        : "=r"(a) : "l"(p));
    return a;
}

__device__ __forceinline__ void mbar_init(uint32_t mbar, uint32_t cnt) {
    asm volatile("mbarrier.init.shared.b64 [%0], %1;" :: "r"(mbar), "r"(cnt) : "memory");
}
__device__ __forceinline__ void mbar_expect_tx(uint32_t mbar, uint32_t bytes) {
    asm volatile("mbarrier.arrive.expect_tx.shared.b64 _, [%0], %1;"
                 :: "r"(mbar), "r"(bytes) : "memory");
}
__device__ __forceinline__ void mbar_wait(uint32_t mbar, uint32_t parity) {
    uint32_t done;
    asm volatile(
        "{\n\t.reg .pred p;\n\t"
        "mbarrier.try_wait.parity.acquire.cta.shared::cta.b64 p, [%1], %2;\n\t"
        "selp.b32 %0, 1, 0, p;\n\t}"
        : "=r"(done) : "r"(mbar), "r"(parity) : "memory");
    if (!done) {
        asm volatile(
            "{\n\t.reg .pred P1;\n\t"
            "W_%=:\n\t"
            "mbarrier.try_wait.parity.acquire.cta.shared::cta.b64 P1, [%0], %1, 0x989680;\n\t"
            "@P1 bra.uni D_%=;\n\t"
            "bra.uni W_%=;\n\t"
            "D_%=:\n\t}"
            :: "r"(mbar), "r"(parity) : "memory");
    }
}
__device__ __forceinline__ void bulk_cp(uint32_t dst, const void* src,
                                        uint32_t bytes, uint32_t mbar) {
    asm volatile(
        "cp.async.bulk.shared::cta.global.mbarrier::complete_tx::bytes [%0], [%1], %2, [%3];"
        :: "r"(dst), "l"(src), "r"(bytes), "r"(mbar) : "memory");
}

__global__ __launch_bounds__(256, 1) void cell_kernel(
    const int*  __restrict__ tim_p,
    const float* __restrict__ X,
    const int*  __restrict__ mask,
    const int*  __restrict__ last_occ,
    const float* __restrict__ Ht,
    const float* __restrict__ c_t,
    const float* __restrict__ W,       // [F, 256, 65]
    const float* __restrict__ Bias,    // [F, 256]
    const float* __restrict__ xTw,     // [F, 64]
    const float* __restrict__ xTb,     // [F, 64]
    const float* __restrict__ delTw,   // [F, 128]
    const float* __restrict__ cinw,    // [F, 64]
    const float* __restrict__ cfw,     // [F, 64]
    const float* __restrict__ coutw,   // [F, 64]
    float* __restrict__ out)
{
    extern __shared__ float s_buf[];           // NSTAGE * STAGE_F floats
    __shared__ float s_gates[G_N];
    __shared__ float s_ct[H_N];
    __shared__ float s_X[MAXNF];
    __shared__ float s_delta[MAXNF];
    __shared__ float s_mf[MAXNF];
    __shared__ __align__(8) uint64_t s_mbar[NSTAGE];

    const int bid = blockIdx.x;
    const int tid = threadIdx.x;
    const int nf  = (F_N - bid + GRID_C - 1) / GRID_C;

    // ---- prologue: per-feature scalars, mask count, c_t, barriers ----
    {
        const int tim = *tim_p;
        const int j = tid;                     // nf <= 68 < 256: single pass
        int mbit = 0;
        if (j < nf) {
            const int f = bid + j * GRID_C;
            s_X[j]     = X[f];
            s_delta[j] = (float)tim - (float)last_occ[f];
            mbit       = (mask[f] == 1);
            s_mf[j]    = mbit ? 1.0f : 0.0f;
        }
        const unsigned b = __ballot_sync(0xFFFFFFFFu, mbit != 0);
        if ((tid & 31) == 0 && b) atomicAdd(&g_cnt, __popc(b));
    }
    if (tid < H_N) s_ct[tid] = c_t[tid];
    if (tid == 0) {
        for (int s = 0; s < NSTAGE; s++) mbar_init(smem_u32(&s_mbar[s]), 1);
    }
    __syncthreads();
    if (tid == 0) {
        asm volatile("fence.proxy.async.shared::cta;" ::: "memory");
    }

    const uint32_t sbase = smem_u32(s_buf);

    auto issue = [&](int j) {
        const int s = j % NSTAGE;
        const size_t f = (size_t)(bid + j * GRID_C);
        const uint32_t d = sbase + (uint32_t)s * STAGE_B;
        const uint32_t mb = smem_u32(&s_mbar[s]);
        mbar_expect_tx(mb, STAGE_B);
        bulk_cp(d + W_OFF * 4,    W     + f * W_ELEMS,   W_ELEMS * 4, mb);
        bulk_cp(d + BIAS_OFF * 4, Bias  + f * G_N,       G_N * 4,     mb);
        bulk_cp(d + HT_OFF * 4,   Ht    + f * H_N,       H_N * 4,     mb);
        bulk_cp(d + XTW_OFF * 4,  xTw   + f * H_N,       H_N * 4,     mb);
        bulk_cp(d + XTB_OFF * 4,  xTb   + f * H_N,       H_N * 4,     mb);
        bulk_cp(d + DELT_OFF * 4, delTw + f * 2 * H_N,   2 * H_N * 4, mb);
        bulk_cp(d + CIN_OFF * 4,  cinw  + f * H_N,       H_N * 4,     mb);
        bulk_cp(d + CF_OFF * 4,   cfw   + f * H_N,       H_N * 4,     mb);
        bulk_cp(d + COUT_OFF * 4, coutw + f * H_N,       H_N * 4,     mb);
    };

    if (tid == 0) {
        const int pre = (nf < NSTAGE) ? nf : NSTAGE;
        for (int j = 0; j < pre; j++) issue(j);
    }

    // ---- main loop ----
    for (int j = 0; j < nf; j++) {
        const int s  = j % NSTAGE;
        const int ph = (j / NSTAGE) & 1;
        mbar_wait(smem_u32(&s_mbar[s]), ph);

        const float* buf = s_buf + (size_t)s * STAGE_F;

        // gates: one row/thread. Row loads: stride-65 -> conflict-free.
        // ht operand: contiguous float4 broadcasts (16B-aligned).
        {
            const float  xv  = s_X[j];
            const float* row = buf + tid * IN_N;
            const float4* ht4 = (const float4*)(buf + HT_OFF);
            float acc = row[0] * xv;
            #pragma unroll
            for (int c = 0; c < 16; c++) {
                const float4 h4 = ht4[c];
                acc += row[1 + 4 * c] * h4.x;
                acc += row[2 + 4 * c] * h4.y;
                acc += row[3 + 4 * c] * h4.z;
                acc += row[4 + 4 * c] * h4.w;
            }
            s_gates[tid] = acc + buf[BIAS_OFF + tid];
        }
        __syncthreads();

        if (tid < H_N) {
            const int h = tid;
            const int f = bid + j * GRID_C;
            const float ct    = s_ct[h];
            const float delta = s_delta[j];

            const float gi     = sigmoidf_(s_gates[h]           + buf[CIN_OFF + h] * ct);
            const float gf     = sigmoidf_(s_gates[H_N + h]     + buf[CF_OFF + h]  * ct);
            const float go_pre = s_gates[2 * H_N + h];
            const float pre_c  = tanhf(s_gates[3 * H_N + h]);

            const float xmT = buf[XTW_OFF + h] * s_X[j] + buf[XTB_OFF + h];
            const float dTt = buf[DELT_OFF + h]        * delta;
            const float dTo = buf[DELT_OFF + H_N + h]  * delta;
            const float Tt  = sigmoidf_(xmT + dTt);

            const float aggc = gf * ct + gi * Tt * pre_c;
            const float go   = sigmoidf_(go_pre + buf[COUT_OFF + h] * aggc + dTo);
            const float hn   = go * tanhf(aggc);

            const float mf = s_mf[j];
            out[OUT_H_OFF + (size_t)f * H_N + h] = mf * hn;
            if (mf != 0.0f) {
                atomicAdd(&g_sumC[h], aggc);
                atomicAdd(&g_sumH[h], hn);
            }
        }
        __syncthreads();   // all reads of stage s complete

        if (tid == 0 && j + NSTAGE < nf) issue(j + NSTAGE);
    }
}

// 1024 threads: 8 threads per hidden row -> 4 float4 LDGs each, max MLP.
__global__ __launch_bounds__(1024) void head_kernel(
    const float* __restrict__ w1,   // [128,128]
    const float* __restrict__ b1,   // [128]
    const float* __restrict__ w2,   // [2,128]
    const float* __restrict__ b2,   // [2]
    float* __restrict__ out)
{
    const int tid = threadIdx.x;
    __shared__ float s_inp[2 * H_N];
    __shared__ float s_part[1024];
    __shared__ float s_hid[2 * H_N];
    __shared__ float s_log[2];

    // build input vector + C_curr output
    if (tid < 2 * H_N) {
        const float cnt = fmaxf((float)g_cnt, 1.0f);
        const float v = ((tid < H_N) ? g_sumC[tid] : g_sumH[tid - H_N]) / cnt;
        s_inp[tid] = v;
        if (tid < H_N) out[OUT_C_OFF + tid] = v;
    }
    __syncthreads();

    // re-zero accumulators for next replay (all reads of them are done)
    if (tid < H_N) { g_sumC[tid] = 0.0f; g_sumH[tid] = 0.0f; }
    if (tid == H_N) g_cnt = 0;

    // partial dots: row r = tid>>3, group g = tid&7 covers cols [16g, 16g+16)
    {
        const int r = tid >> 3;
        const int g = tid & 7;
        const float4* wrow = (const float4*)(w1 + r * 2 * H_N) + g * 4;
        const float4* in4  = (const float4*)s_inp + g * 4;
        float acc = 0.0f;
        #pragma unroll
        for (int q = 0; q < 4; q++) {
            const float4 w4 = wrow[q];
            const float4 i4 = in4[q];
            acc += w4.x * i4.x + w4.y * i4.y + w4.z * i4.z + w4.w * i4.w;
        }
        s_part[tid] = acc;
    }
    __syncthreads();

    // reduce 8 partials per row, add bias, relu
    if (tid < 2 * H_N) {
        const float* p = s_part + tid * 8;
        float acc = b1[tid];
        #pragma unroll
        for (int q = 0; q < 8; q++) acc += p[q];
        s_hid[tid] = fmaxf(acc, 0.0f);
    }
    __syncthreads();

    // logits: warp 0 -> class 0, warp 1 -> class 1 (shuffle reduce)
    if (tid < 64) {
        const int cls  = tid >> 5;
        const int lane = tid & 31;
        const float4 w4a = ((const float4*)(w2 + cls * 2 * H_N))[lane];
        const float* hp = s_hid + lane * 4;
        float acc = w4a.x * hp[0] + w4a.y * hp[1] + w4a.z * hp[2] + w4a.w * hp[3];
        #pragma unroll
        for (int o = 16; o > 0; o >>= 1)
            acc += __shfl_xor_sync(0xFFFFFFFFu, acc, o);
        if (lane == 0) s_log[cls] = acc + b2[cls];
    }
    __syncthreads();

    if (tid == 0) {
        const float m  = fmaxf(s_log[0], s_log[1]);
        const float e0 = expf(s_log[0] - m);
        const float e1 = expf(s_log[1] - m);
        const float inv = 1.0f / (e0 + e1);
        out[OUT_PRED_OFF + 0] = e0 * inv;
        out[OUT_PRED_OFF + 1] = e1 * inv;
    }
}

extern "C" void kernel_launch(void* const* d_in, const int* in_sizes, int n_in,
                              void* d_out, int out_size) {
    const int*   tim       = (const int*)  d_in[0];
    const float* X         = (const float*)d_in[1];
    // d_in[2] = X_hap (unused)
    const int*   mask      = (const int*)  d_in[3];
    const int*   last_occ  = (const int*)  d_in[4];
    const float* Ht        = (const float*)d_in[5];
    // d_in[6] = Ct (unused)
    const float* c_t       = (const float*)d_in[7];
    const float* W         = (const float*)d_in[8];
    const float* Bias      = (const float*)d_in[9];
    const float* xTw       = (const float*)d_in[10];
    const float* xTb       = (const float*)d_in[11];
    const float* delTw     = (const float*)d_in[12];
    const float* cinw      = (const float*)d_in[13];
    const float* cfw       = (const float*)d_in[14];
    const float* coutw     = (const float*)d_in[15];
    const float* w1        = (const float*)d_in[16];
    const float* b1        = (const float*)d_in[17];
    const float* w2        = (const float*)d_in[18];
    const float* b2        = (const float*)d_in[19];
    float* out = (float*)d_out;

    const int smem_bytes = NSTAGE * STAGE_B;   // 208896
    cudaFuncSetAttribute(cell_kernel,
                         cudaFuncAttributeMaxDynamicSharedMemorySize, smem_bytes);

    cell_kernel<<<GRID_C, 256, smem_bytes>>>(tim, X, mask, last_occ, Ht, c_t,
                                             W, Bias, xTw, xTb, delTw,
                                             cinw, cfw, coutw, out);
    head_kernel<<<1, 1024>>>(w1, b1, w2, b2, out);
}